// round 1
// baseline (speedup 1.0000x reference)
#include <cuda_runtime.h>

// ============================================================================
// AttentionGate3D — round 1 baseline
//   P1: yg = Wg·g, yx = Wx·x   (fp32 f32x2 GEMM, + per-(n,i) sum/sumsq stats)
//   P2: fold stats+gamma/beta into per-channel affine coefs A,B
//   P3: z[n,p] = sum_i Wpsi[i]*relu(A_g*yg + B_g + A_x*yx + B_x)  (+ z stats)
//   P4: alpha[n,p] = sigmoid(gamma_p*normz + beta_p)
//   P5: out = x * alpha
// ============================================================================

#define EPS 1e-5f

constexpr int NB = 2;
constexpr int G  = 256;
constexpr int XC = 128;
constexpr int I  = 128;
constexpr int S  = 32 * 64 * 64;   // 131072
constexpr int BP = 128;            // points per GEMM block
constexpr int BK = 16;             // K chunk

// ---- scratch (device globals; no runtime allocation allowed) ----
__device__ float d_yg[NB * I * S];     // 134 MB
__device__ float d_yx[NB * I * S];     // 134 MB
__device__ float d_z[NB * S];
__device__ float d_alpha[NB * S];
__device__ float d_sum_g[NB * I];
__device__ float d_sq_g [NB * I];
__device__ float d_sum_x[NB * I];
__device__ float d_sq_x [NB * I];
__device__ float d_zstat[2 * NB];      // [sum_n0, sum_n1, sq_n0, sq_n1]
__device__ float d_cAg[NB * I], d_cBg[NB * I];
__device__ float d_cAx[NB * I], d_cBx[NB * I];

// ---- f32x2 packed-FMA helpers (sm_100+ only; doubles FP32 MAC rate) ----
__device__ __forceinline__ unsigned long long pack2(float x) {
    unsigned long long r;
    asm("mov.b64 %0, {%1, %1};" : "=l"(r) : "f"(x));
    return r;
}
__device__ __forceinline__ void ffma2(unsigned long long& d,
                                      unsigned long long a,
                                      unsigned long long b) {
    asm("fma.rn.f32x2 %0, %1, %2, %0;" : "+l"(d) : "l"(a), "l"(b));
}
union U64F2 { unsigned long long u; float2 f; };

// ---- K0: zero the stat accumulators (graph replays must restart clean) ----
__global__ void k_zero() {
    int t = threadIdx.x;
    if (t < NB * I) {
        d_sum_g[t] = 0.f; d_sq_g[t] = 0.f;
        d_sum_x[t] = 0.f; d_sq_x[t] = 0.f;
    }
    if (t < 2 * NB) d_zstat[t] = 0.f;
}

// ---- K1/K2: GEMM  y[n,i,p] = sum_c W[i,c] * src[n,c,p], plus stats --------
// Block: 128 points x all 128 i.  Thread (tx,ty): 8 i x 8 p (4 f32x2 pairs).
template<int K, bool ISG>
__global__ void __launch_bounds__(256, 2) k_gemm(const float* __restrict__ src,
                                                 const float* __restrict__ W) {
    __shared__ unsigned long long sW2[BK][I + 1];  // W duplicated into pairs
    __shared__ float sG[BK][BP];

    float* yout = ISG ? d_yg    : d_yx;
    float* ssum = ISG ? d_sum_g : d_sum_x;
    float* ssq  = ISG ? d_sq_g  : d_sq_x;

    const int tid = threadIdx.x;
    const int tx  = tid & 15;    // p-pair group
    const int ty  = tid >> 4;    // i group
    const int n   = blockIdx.y;
    const int p0  = blockIdx.x * BP;
    const float* srcn = src + (size_t)n * K * S + p0;

    unsigned long long acc[8][4];
#pragma unroll
    for (int j = 0; j < 8; j++)
#pragma unroll
        for (int q = 0; q < 4; q++) acc[j][q] = 0ull;

    for (int c0 = 0; c0 < K; c0 += BK) {
        // stage src tile [BK x BP] (fully coalesced)
#pragma unroll
        for (int v = 0; v < 8; v++) {
            int idx = tid + v * 256;
            int cc = idx >> 7, pp = idx & 127;
            sG[cc][pp] = srcn[(size_t)(c0 + cc) * S + pp];
        }
        // stage W tile [BK x I], each value duplicated into a f32x2 pair
#pragma unroll
        for (int v = 0; v < 8; v++) {
            int idx = tid + v * 256;
            int ii = idx >> 4, cc = idx & 15;
            sW2[cc][ii] = pack2(W[ii * K + c0 + cc]);
        }
        __syncthreads();
#pragma unroll
        for (int c = 0; c < BK; c++) {
            unsigned long long gv[4];
#pragma unroll
            for (int q = 0; q < 4; q++)
                gv[q] = *reinterpret_cast<const unsigned long long*>(
                            &sG[c][2 * (tx + 16 * q)]);
#pragma unroll
            for (int j = 0; j < 8; j++) {
                unsigned long long wv = sW2[c][ty * 8 + j];
#pragma unroll
                for (int q = 0; q < 4; q++) ffma2(acc[j][q], wv, gv[q]);
            }
        }
        __syncthreads();
    }

    // write y + per-i partial stats (reduce across the 16 tx lanes)
    float* yn = yout + (size_t)n * I * S + p0;
#pragma unroll
    for (int j = 0; j < 8; j++) {
        int i = ty * 8 + j;
        float s = 0.f, q2 = 0.f;
        float* row = yn + (size_t)i * S;
#pragma unroll
        for (int q = 0; q < 4; q++) {
            U64F2 u; u.u = acc[j][q];
            *reinterpret_cast<float2*>(&row[2 * (tx + 16 * q)]) = u.f;
            s  += u.f.x + u.f.y;
            q2 += u.f.x * u.f.x + u.f.y * u.f.y;
        }
#pragma unroll
        for (int off = 8; off > 0; off >>= 1) {
            s  += __shfl_down_sync(0xFFFFFFFFu, s,  off, 16);
            q2 += __shfl_down_sync(0xFFFFFFFFu, q2, off, 16);
        }
        if (tx == 0) {
            atomicAdd(&ssum[n * I + i], s);
            atomicAdd(&ssq [n * I + i], q2);
        }
    }
}

// ---- K3: fold stats + gamma/beta into affine coefs ------------------------
__global__ void k_coefs(const float* __restrict__ gam_g, const float* __restrict__ bet_g,
                        const float* __restrict__ gam_x, const float* __restrict__ bet_x) {
    int t = threadIdx.x;
    if (t < NB * I) {
        int i = t & (I - 1);
        const float inv = 1.f / (float)S;
        float m   = d_sum_g[t] * inv;
        float var = fmaxf(d_sq_g[t] * inv - m * m, 0.f);
        float A   = gam_g[i] * rsqrtf(var + EPS);
        d_cAg[t] = A; d_cBg[t] = bet_g[i] - m * A;
        m   = d_sum_x[t] * inv;
        var = fmaxf(d_sq_x[t] * inv - m * m, 0.f);
        A   = gam_x[i] * rsqrtf(var + EPS);
        d_cAx[t] = A; d_cBx[t] = bet_x[i] - m * A;
    }
}

// ---- K4: z = Wpsi . relu(A_g*yg+B_g + A_x*yx+B_x), plus z stats ------------
__global__ void __launch_bounds__(256) k_combine(const float* __restrict__ Wpsi) {
    __shared__ float sc[5 * I];
    const int tid = threadIdx.x;
    const int n   = blockIdx.y;
    const int p0  = blockIdx.x * 1024;
    if (tid < I) {
        sc[tid]         = d_cAg[n * I + tid];
        sc[I + tid]     = d_cBg[n * I + tid];
        sc[2 * I + tid] = d_cAx[n * I + tid];
        sc[3 * I + tid] = d_cBx[n * I + tid];
        sc[4 * I + tid] = Wpsi[tid];
    }
    __syncthreads();
    const float* ygb = d_yg + (size_t)n * I * S + p0 + tid * 4;
    const float* yxb = d_yx + (size_t)n * I * S + p0 + tid * 4;
    float4 za = make_float4(0.f, 0.f, 0.f, 0.f);
#pragma unroll 4
    for (int i = 0; i < I; i++) {
        float4 a = *reinterpret_cast<const float4*>(ygb + (size_t)i * S);
        float4 b = *reinterpret_cast<const float4*>(yxb + (size_t)i * S);
        float Ag = sc[i], Ax = sc[2 * I + i];
        float C  = sc[I + i] + sc[3 * I + i];
        float w  = sc[4 * I + i];
        za.x += w * fmaxf(fmaf(Ag, a.x, fmaf(Ax, b.x, C)), 0.f);
        za.y += w * fmaxf(fmaf(Ag, a.y, fmaf(Ax, b.y, C)), 0.f);
        za.z += w * fmaxf(fmaf(Ag, a.z, fmaf(Ax, b.z, C)), 0.f);
        za.w += w * fmaxf(fmaf(Ag, a.w, fmaf(Ax, b.w, C)), 0.f);
    }
    *reinterpret_cast<float4*>(&d_z[n * S + p0 + tid * 4]) = za;

    float s = za.x + za.y + za.z + za.w;
    float q = za.x * za.x + za.y * za.y + za.z * za.z + za.w * za.w;
#pragma unroll
    for (int off = 16; off > 0; off >>= 1) {
        s += __shfl_down_sync(0xFFFFFFFFu, s, off);
        q += __shfl_down_sync(0xFFFFFFFFu, q, off);
    }
    __shared__ float rs[8], rq[8];
    int wid = tid >> 5, lane = tid & 31;
    if (lane == 0) { rs[wid] = s; rq[wid] = q; }
    __syncthreads();
    if (tid == 0) {
        float st = 0.f, qt = 0.f;
#pragma unroll
        for (int w2 = 0; w2 < 8; w2++) { st += rs[w2]; qt += rq[w2]; }
        atomicAdd(&d_zstat[n], st);
        atomicAdd(&d_zstat[NB + n], qt);
    }
}

// ---- K5: alpha = sigmoid(norm(z)*gamma_p + beta_p) -------------------------
__global__ void k_alpha(const float* __restrict__ gam_p, const float* __restrict__ bet_p) {
    const int n   = blockIdx.y;
    const int idx = blockIdx.x * blockDim.x + threadIdx.x;   // float4 index
    const float inv = 1.f / (float)S;
    float m   = d_zstat[n] * inv;
    float var = fmaxf(d_zstat[NB + n] * inv - m * m, 0.f);
    float A   = gam_p[0] * rsqrtf(var + EPS);
    float B   = bet_p[0] - m * A;
    float4 z = *reinterpret_cast<const float4*>(&d_z[n * S + idx * 4]);
    float4 al;
    al.x = 1.f / (1.f + expf(-fmaf(A, z.x, B)));
    al.y = 1.f / (1.f + expf(-fmaf(A, z.y, B)));
    al.z = 1.f / (1.f + expf(-fmaf(A, z.z, B)));
    al.w = 1.f / (1.f + expf(-fmaf(A, z.w, B)));
    *reinterpret_cast<float4*>(&d_alpha[n * S + idx * 4]) = al;
}

// ---- K6: out = x * alpha ----------------------------------------------------
__global__ void k_mul(const float* __restrict__ x, float* __restrict__ out) {
    const int idx = blockIdx.x * blockDim.x + threadIdx.x;   // float4 index
    const int n   = idx >> 22;              // 128*S/4 = 2^22 float4 per n
    const int p4  = idx & (S / 4 - 1);
    float4 xv = reinterpret_cast<const float4*>(x)[idx];
    float4 av = *reinterpret_cast<const float4*>(&d_alpha[n * S + p4 * 4]);
    float4 o  = make_float4(xv.x * av.x, xv.y * av.y, xv.z * av.z, xv.w * av.w);
    reinterpret_cast<float4*>(out)[idx] = o;
}

// ============================================================================
extern "C" void kernel_launch(void* const* d_in, const int* in_sizes, int n_in,
                              void* d_out, int out_size) {
    const float* g     = (const float*)d_in[0];
    const float* x     = (const float*)d_in[1];
    const float* Wg    = (const float*)d_in[2];
    const float* Wx    = (const float*)d_in[3];
    const float* Wpsi  = (const float*)d_in[4];
    const float* gam_g = (const float*)d_in[5];
    const float* bet_g = (const float*)d_in[6];
    const float* gam_x = (const float*)d_in[7];
    const float* bet_x = (const float*)d_in[8];
    const float* gam_p = (const float*)d_in[9];
    const float* bet_p = (const float*)d_in[10];
    float* out = (float*)d_out;

    k_zero<<<1, 256>>>();

    dim3 ggrid(S / BP, NB);                       // 1024 x 2
    k_gemm<G,  true ><<<ggrid, 256>>>(g, Wg);
    k_gemm<XC, false><<<ggrid, 256>>>(x, Wx);

    k_coefs<<<1, 256>>>(gam_g, bet_g, gam_x, bet_x);

    dim3 cgrid(S / 1024, NB);                     // 128 x 2
    k_combine<<<cgrid, 256>>>(Wpsi);

    dim3 agrid(S / 1024, NB);                     // 128 x 2 (256 thr * 4 elems)
    k_alpha<<<agrid, 256>>>(gam_p, bet_p);

    int total4 = NB * XC * S / 4;                 // 16,777,216
    k_mul<<<total4 / 256, 256>>>(x, out);
}

// round 2
// speedup vs baseline: 2.4636x; 2.4636x over previous
#include <cuda_runtime.h>
#include <cuda_fp16.h>

// ============================================================================
// AttentionGate3D — round 2: fp16 HMMA (mma.sync m16n8k16) GEMMs, fp16 y store
//   P1: yg = Wg·g, yx = Wx·x  (fp16 in, fp32 acc, fp16 out) + per-(n,i) stats
//   P2: fold stats+gamma/beta into per-channel affine coefs A,B
//   P3: z[n,p] = sum_i Wpsi[i]*relu(Ag*yg+Bg + Ax*yx+Bx)  (+ z stats)
//   P4: alpha = sigmoid(gamma_p*normz + beta_p)
//   P5: out = x * alpha
// ============================================================================

#define EPS 1e-5f

constexpr int NB = 2;
constexpr int G  = 256;
constexpr int XC = 128;
constexpr int I  = 128;
constexpr int S  = 32 * 64 * 64;   // 131072

// ---- scratch (device globals; no runtime allocation allowed) ----
__device__ __half d_yg[NB * I * S];     // 67 MB
__device__ __half d_yx[NB * I * S];     // 67 MB
__device__ float  d_z[NB * S];
__device__ float  d_alpha[NB * S];
__device__ float  d_sum_g[NB * I];
__device__ float  d_sq_g [NB * I];
__device__ float  d_sum_x[NB * I];
__device__ float  d_sq_x [NB * I];
__device__ float  d_zstat[2 * NB];
__device__ float  d_cAg[NB * I], d_cBg[NB * I];
__device__ float  d_cAx[NB * I], d_cBx[NB * I];

// ---- K0: zero the accumulators (graph replays must restart clean) ----
__global__ void k_zero() {
    int t = threadIdx.x;
    if (t < NB * I) {
        d_sum_g[t] = 0.f; d_sq_g[t] = 0.f;
        d_sum_x[t] = 0.f; d_sq_x[t] = 0.f;
    }
    if (t < 2 * NB) d_zstat[t] = 0.f;
}

// ---- MMA helpers ----
__device__ __forceinline__ void ldsm_x4(unsigned (&r)[4], unsigned addr) {
    asm volatile("ldmatrix.sync.aligned.m8n8.x4.shared.b16 {%0,%1,%2,%3}, [%4];"
        : "=r"(r[0]), "=r"(r[1]), "=r"(r[2]), "=r"(r[3]) : "r"(addr));
}
__device__ __forceinline__ void mma16816(float (&d)[4], const unsigned (&a)[4],
                                         const unsigned (&b)[2]) {
    asm volatile("mma.sync.aligned.m16n8k16.row.col.f32.f16.f16.f32 "
        "{%0,%1,%2,%3}, {%4,%5,%6,%7}, {%8,%9}, {%0,%1,%2,%3};"
        : "+f"(d[0]), "+f"(d[1]), "+f"(d[2]), "+f"(d[3])
        : "r"(a[0]), "r"(a[1]), "r"(a[2]), "r"(a[3]), "r"(b[0]), "r"(b[1]));
}
union H2U { __half2 h; unsigned u; };
__device__ __forceinline__ unsigned pack2h(float a, float b) {
    H2U v; v.h = __floats2half2_rn(a, b); return v.u;
}

// ---- K1/K2: GEMM  y[n,i,p] = sum_c W[i,c]*src[n,c,p]  (fp16 MMA) ----------
// CTA tile: M=128 (all i) x N=128 points, full K. 8 warps = 2(M) x 4(N).
// SMEM: sA = W fp16 [128][K] (swizzled 16B chunks), sB = src^T fp16 [128][64].
template<int K, bool ISG>
__global__ void __launch_bounds__(256, 2) k_gemm(const float* __restrict__ src,
                                                 const float* __restrict__ W) {
    extern __shared__ __align__(16) char smem[];
    __half* sA = reinterpret_cast<__half*>(smem);                  // 128*K
    __half* sB = reinterpret_cast<__half*>(smem) + 128 * K;        // 128*64
    const unsigned sA32 = (unsigned)__cvta_generic_to_shared(sA);
    const unsigned sB32 = (unsigned)__cvta_generic_to_shared(sB);

    __half* yout = ISG ? d_yg    : d_yx;
    float*  ssum = ISG ? d_sum_g : d_sum_x;
    float*  ssq  = ISG ? d_sq_g  : d_sq_x;

    const int tid  = threadIdx.x;
    const int warp = tid >> 5, lane = tid & 31;
    const int wm = warp >> 2, wn = warp & 3;          // warp tile: 64 M x 32 N
    const int n  = blockIdx.y;
    const int p0 = blockIdx.x * 128;
    const float* srcn = src + (size_t)n * K * S + p0;

    // ---- stage all of W (fp32 -> fp16, swizzled) ----
    constexpr int CHR = K / 8;   // 16B chunks per row
    for (int idx = tid; idx < 128 * CHR; idx += 256) {
        int r = idx / CHR, k16 = idx % CHR;
        const float4* wp = reinterpret_cast<const float4*>(W + r * K + k16 * 8);
        float4 w0 = wp[0], w1 = wp[1];
        uint4 u;
        u.x = pack2h(w0.x, w0.y); u.y = pack2h(w0.z, w0.w);
        u.z = pack2h(w1.x, w1.y); u.w = pack2h(w1.z, w1.w);
        int phys = (k16 & ~7) | ((k16 & 7) ^ (r & 7));
        *reinterpret_cast<uint4*>(sA + r * K + phys * 8) = u;
    }

    float acc[4][4][4];
#pragma unroll
    for (int a = 0; a < 4; a++)
#pragma unroll
        for (int b = 0; b < 4; b++)
#pragma unroll
            for (int c = 0; c < 4; c++) acc[a][b][c] = 0.f;

    const int pstage = tid & 127;       // staging: point row
    const int jh     = tid >> 7;        // staging: chunk half

    for (int c0 = 0; c0 < K; c0 += 64) {
        __syncthreads();
        // ---- stage src tile [64 c x 128 p] as sB[p][c] fp16, swizzled ----
#pragma unroll
        for (int j = jh * 4; j < jh * 4 + 4; j++) {
            float v[8];
#pragma unroll
            for (int e = 0; e < 8; e++)
                v[e] = srcn[(size_t)(c0 + j * 8 + e) * S + pstage];
            uint4 u;
            u.x = pack2h(v[0], v[1]); u.y = pack2h(v[2], v[3]);
            u.z = pack2h(v[4], v[5]); u.w = pack2h(v[6], v[7]);
            int phys = j ^ (pstage & 7);
            *reinterpret_cast<uint4*>(sB + pstage * 64 + phys * 8) = u;
        }
        __syncthreads();

#pragma unroll
        for (int ks = 0; ks < 4; ks++) {
            unsigned afr[4][4];
#pragma unroll
            for (int tm = 0; tm < 4; tm++) {
                int row = wm * 64 + tm * 16 + (lane & 15);
                int kch = c0 / 8 + ks * 2 + (lane >> 4);
                int phys = (kch & ~7) | ((kch & 7) ^ (row & 7));
                ldsm_x4(afr[tm], sA32 + (unsigned)(row * K * 2 + phys * 16));
            }
            unsigned bfr[4][2];
#pragma unroll
            for (int tp = 0; tp < 2; tp++) {
                int p = wn * 32 + tp * 16 + ((lane >> 4) * 8) + (lane & 7);
                int kch = ks * 2 + ((lane >> 3) & 1);
                int phys = kch ^ (p & 7);
                unsigned r4[4];
                ldsm_x4(r4, sB32 + (unsigned)(p * 128 + phys * 16));
                bfr[tp * 2][0] = r4[0];     bfr[tp * 2][1] = r4[1];
                bfr[tp * 2 + 1][0] = r4[2]; bfr[tp * 2 + 1][1] = r4[3];
            }
#pragma unroll
            for (int tm = 0; tm < 4; tm++)
#pragma unroll
                for (int tn = 0; tn < 4; tn++)
                    mma16816(acc[tm][tn], afr[tm], bfr[tn]);
        }
    }

    // ---- epilogue: fp16 store + per-i stats from fp32 accumulators ----
    __half* yn = yout + (size_t)n * I * S + p0;
#pragma unroll
    for (int tm = 0; tm < 4; tm++) {
        int r1 = wm * 64 + tm * 16 + (lane >> 2);
        float s1 = 0.f, q1 = 0.f, s2 = 0.f, q2 = 0.f;
#pragma unroll
        for (int tn = 0; tn < 4; tn++) {
            float* c = acc[tm][tn];
            int col = wn * 32 + tn * 8 + (lane & 3) * 2;
            *reinterpret_cast<__half2*>(yn + (size_t)r1 * S + col) =
                __floats2half2_rn(c[0], c[1]);
            *reinterpret_cast<__half2*>(yn + (size_t)(r1 + 8) * S + col) =
                __floats2half2_rn(c[2], c[3]);
            s1 += c[0] + c[1]; q1 += c[0] * c[0] + c[1] * c[1];
            s2 += c[2] + c[3]; q2 += c[2] * c[2] + c[3] * c[3];
        }
#pragma unroll
        for (int off = 2; off > 0; off >>= 1) {
            s1 += __shfl_down_sync(0xFFFFFFFFu, s1, off, 4);
            q1 += __shfl_down_sync(0xFFFFFFFFu, q1, off, 4);
            s2 += __shfl_down_sync(0xFFFFFFFFu, s2, off, 4);
            q2 += __shfl_down_sync(0xFFFFFFFFu, q2, off, 4);
        }
        if ((lane & 3) == 0) {
            atomicAdd(&ssum[n * I + r1], s1);
            atomicAdd(&ssq [n * I + r1], q1);
            atomicAdd(&ssum[n * I + r1 + 8], s2);
            atomicAdd(&ssq [n * I + r1 + 8], q2);
        }
    }
}

// ---- K3: fold stats + gamma/beta into affine coefs ------------------------
__global__ void k_coefs(const float* __restrict__ gam_g, const float* __restrict__ bet_g,
                        const float* __restrict__ gam_x, const float* __restrict__ bet_x) {
    int t = threadIdx.x;
    if (t < NB * I) {
        int i = t & (I - 1);
        const float inv = 1.f / (float)S;
        float m   = d_sum_g[t] * inv;
        float var = fmaxf(d_sq_g[t] * inv - m * m, 0.f);
        float A   = gam_g[i] * rsqrtf(var + EPS);
        d_cAg[t] = A; d_cBg[t] = bet_g[i] - m * A;
        m   = d_sum_x[t] * inv;
        var = fmaxf(d_sq_x[t] * inv - m * m, 0.f);
        A   = gam_x[i] * rsqrtf(var + EPS);
        d_cAx[t] = A; d_cBx[t] = bet_x[i] - m * A;
    }
}

// ---- K4: z = Wpsi . relu(Ag*yg+Bg + Ax*yx+Bx), plus z stats ----------------
__global__ void __launch_bounds__(256) k_combine(const float* __restrict__ Wpsi) {
    __shared__ float sc[5 * I];
    const int tid = threadIdx.x;
    const int n   = blockIdx.y;
    const int p0  = blockIdx.x * 2048;
    if (tid < I) {
        sc[tid]         = d_cAg[n * I + tid];
        sc[I + tid]     = d_cBg[n * I + tid];
        sc[2 * I + tid] = d_cAx[n * I + tid];
        sc[3 * I + tid] = d_cBx[n * I + tid];
        sc[4 * I + tid] = Wpsi[tid];
    }
    __syncthreads();
    const __half* ygb = d_yg + (size_t)n * I * S + p0 + tid * 8;
    const __half* yxb = d_yx + (size_t)n * I * S + p0 + tid * 8;
    float za[8];
#pragma unroll
    for (int j = 0; j < 8; j++) za[j] = 0.f;

#pragma unroll 2
    for (int i = 0; i < I; i++) {
        uint4 ua = *reinterpret_cast<const uint4*>(ygb + (size_t)i * S);
        uint4 ub = *reinterpret_cast<const uint4*>(yxb + (size_t)i * S);
        float Ag = sc[i], Ax = sc[2 * I + i];
        float C  = sc[I + i] + sc[3 * I + i];
        float w  = sc[4 * I + i];
        const unsigned* pa = &ua.x;
        const unsigned* pb = &ub.x;
#pragma unroll
        for (int q = 0; q < 4; q++) {
            H2U ha, hb; ha.u = pa[q]; hb.u = pb[q];
            float2 fa = __half22float2(ha.h);
            float2 fb = __half22float2(hb.h);
            za[2 * q]     += w * fmaxf(fmaf(Ag, fa.x, fmaf(Ax, fb.x, C)), 0.f);
            za[2 * q + 1] += w * fmaxf(fmaf(Ag, fa.y, fmaf(Ax, fb.y, C)), 0.f);
        }
    }
    float4* zp = reinterpret_cast<float4*>(&d_z[n * S + p0 + tid * 8]);
    zp[0] = make_float4(za[0], za[1], za[2], za[3]);
    zp[1] = make_float4(za[4], za[5], za[6], za[7]);

    float s = 0.f, q = 0.f;
#pragma unroll
    for (int j = 0; j < 8; j++) { s += za[j]; q += za[j] * za[j]; }
#pragma unroll
    for (int off = 16; off > 0; off >>= 1) {
        s += __shfl_down_sync(0xFFFFFFFFu, s, off);
        q += __shfl_down_sync(0xFFFFFFFFu, q, off);
    }
    __shared__ float rs[8], rq[8];
    int wid = tid >> 5, ln = tid & 31;
    if (ln == 0) { rs[wid] = s; rq[wid] = q; }
    __syncthreads();
    if (tid == 0) {
        float st = 0.f, qt = 0.f;
#pragma unroll
        for (int w2 = 0; w2 < 8; w2++) { st += rs[w2]; qt += rq[w2]; }
        atomicAdd(&d_zstat[n], st);
        atomicAdd(&d_zstat[NB + n], qt);
    }
}

// ---- K5: alpha = sigmoid(norm(z)*gamma_p + beta_p) -------------------------
__global__ void k_alpha(const float* __restrict__ gam_p, const float* __restrict__ bet_p) {
    const int n   = blockIdx.y;
    const int idx = blockIdx.x * blockDim.x + threadIdx.x;
    const float inv = 1.f / (float)S;
    float m   = d_zstat[n] * inv;
    float var = fmaxf(d_zstat[NB + n] * inv - m * m, 0.f);
    float A   = gam_p[0] * rsqrtf(var + EPS);
    float B   = bet_p[0] - m * A;
    float4 z = *reinterpret_cast<const float4*>(&d_z[n * S + idx * 4]);
    float4 al;
    al.x = 1.f / (1.f + expf(-fmaf(A, z.x, B)));
    al.y = 1.f / (1.f + expf(-fmaf(A, z.y, B)));
    al.z = 1.f / (1.f + expf(-fmaf(A, z.z, B)));
    al.w = 1.f / (1.f + expf(-fmaf(A, z.w, B)));
    *reinterpret_cast<float4*>(&d_alpha[n * S + idx * 4]) = al;
}

// ---- K6: out = x * alpha ----------------------------------------------------
__global__ void k_mul(const float* __restrict__ x, float* __restrict__ out) {
    const int idx = blockIdx.x * blockDim.x + threadIdx.x;   // float4 index
    const int n   = idx >> 22;
    const int p4  = idx & (S / 4 - 1);
    float4 xv = reinterpret_cast<const float4*>(x)[idx];
    float4 av = *reinterpret_cast<const float4*>(&d_alpha[n * S + p4 * 4]);
    reinterpret_cast<float4*>(out)[idx] =
        make_float4(xv.x * av.x, xv.y * av.y, xv.z * av.z, xv.w * av.w);
}

// ============================================================================
extern "C" void kernel_launch(void* const* d_in, const int* in_sizes, int n_in,
                              void* d_out, int out_size) {
    const float* g     = (const float*)d_in[0];
    const float* x     = (const float*)d_in[1];
    const float* Wg    = (const float*)d_in[2];
    const float* Wx    = (const float*)d_in[3];
    const float* Wpsi  = (const float*)d_in[4];
    const float* gam_g = (const float*)d_in[5];
    const float* bet_g = (const float*)d_in[6];
    const float* gam_x = (const float*)d_in[7];
    const float* bet_x = (const float*)d_in[8];
    const float* gam_p = (const float*)d_in[9];
    const float* bet_p = (const float*)d_in[10];
    float* out = (float*)d_out;

    const int SMEM_G = 128 * G  * 2 + 128 * 64 * 2;   // 81920
    const int SMEM_X = 128 * XC * 2 + 128 * 64 * 2;   // 49152
    cudaFuncSetAttribute(k_gemm<G,  true >,
                         cudaFuncAttributeMaxDynamicSharedMemorySize, SMEM_G);
    cudaFuncSetAttribute(k_gemm<XC, false>,
                         cudaFuncAttributeMaxDynamicSharedMemorySize, SMEM_X);

    k_zero<<<1, 256>>>();

    dim3 ggrid(S / 128, NB);                       // 1024 x 2
    k_gemm<G,  true ><<<ggrid, 256, SMEM_G>>>(g, Wg);
    k_gemm<XC, false><<<ggrid, 256, SMEM_X>>>(x, Wx);

    k_coefs<<<1, 256>>>(gam_g, bet_g, gam_x, bet_x);

    dim3 cgrid(S / 2048, NB);                      // 64 x 2
    k_combine<<<cgrid, 256>>>(Wpsi);

    dim3 agrid(S / 1024, NB);                      // 128 x 2
    k_alpha<<<agrid, 256>>>(gam_p, bet_p);

    int total4 = NB * XC * S / 4;                  // 16,777,216 float4
    k_mul<<<total4 / 256, 256>>>(x, out);
}

// round 3
// speedup vs baseline: 2.6295x; 1.0673x over previous
#include <cuda_runtime.h>
#include <cuda_fp16.h>

// ============================================================================
// AttentionGate3D — round 3: software-pipelined fp16 HMMA GEMMs,
// fused alpha+mul, higher-ILP combine.
// ============================================================================

#define EPS 1e-5f

constexpr int NB = 2;
constexpr int G  = 256;
constexpr int XC = 128;
constexpr int I  = 128;
constexpr int S  = 32 * 64 * 64;   // 131072
constexpr int KC = 32;             // K chunk per pipeline stage
constexpr int SBROW = 40;          // padded sB row (halves): 32 + 8 pad

// ---- scratch ----
__device__ __half d_yg[NB * I * S];
__device__ __half d_yx[NB * I * S];
__device__ float  d_z[NB * S];
__device__ float  d_sum_g[NB * I];
__device__ float  d_sq_g [NB * I];
__device__ float  d_sum_x[NB * I];
__device__ float  d_sq_x [NB * I];
__device__ float  d_zstat[2 * NB];
__device__ float  d_cAg[NB * I], d_cBg[NB * I];
__device__ float  d_cAx[NB * I], d_cBx[NB * I];

__global__ void k_zero() {          // gemm stat accumulators
    int t = threadIdx.x;
    if (t < NB * I) {
        d_sum_g[t] = 0.f; d_sq_g[t] = 0.f;
        d_sum_x[t] = 0.f; d_sq_x[t] = 0.f;
    }
}
__global__ void k_zero2() {         // z stat accumulators
    int t = threadIdx.x;
    if (t < 2 * NB) d_zstat[t] = 0.f;
}

// ---- MMA helpers ----
__device__ __forceinline__ void ldsm_x4(unsigned (&r)[4], unsigned addr) {
    asm volatile("ldmatrix.sync.aligned.m8n8.x4.shared.b16 {%0,%1,%2,%3}, [%4];"
        : "=r"(r[0]), "=r"(r[1]), "=r"(r[2]), "=r"(r[3]) : "r"(addr));
}
__device__ __forceinline__ void mma16816(float (&d)[4], const unsigned (&a)[4],
                                         const unsigned (&b)[2]) {
    asm volatile("mma.sync.aligned.m16n8k16.row.col.f32.f16.f16.f32 "
        "{%0,%1,%2,%3}, {%4,%5,%6,%7}, {%8,%9}, {%0,%1,%2,%3};"
        : "+f"(d[0]), "+f"(d[1]), "+f"(d[2]), "+f"(d[3])
        : "r"(a[0]), "r"(a[1]), "r"(a[2]), "r"(a[3]), "r"(b[0]), "r"(b[1]));
}
union H2U { __half2 h; unsigned u; };
__device__ __forceinline__ unsigned pack2h(float a, float b) {
    H2U v; v.h = __floats2half2_rn(a, b); return v.u;
}

// ---- GEMM: y[n,i,p] = sum_c W[i,c]*src[n,c,p], fp16 MMA, pipelined --------
// CTA tile M=128 x N=128 points; 8 warps = 2(M) x 4(N), warp 64M x 32N.
// K pipelined in KC=32 chunks with double-buffered sB + register prefetch.
template<int K, bool ISG>
__global__ void __launch_bounds__(256, 2) k_gemm(const float* __restrict__ src,
                                                 const float* __restrict__ W) {
    extern __shared__ __align__(16) char smem[];
    __half* sA = reinterpret_cast<__half*>(smem);                   // 128*K
    __half* sB = reinterpret_cast<__half*>(smem) + 128 * K;         // 2*128*SBROW
    const unsigned sA32 = (unsigned)__cvta_generic_to_shared(sA);
    const unsigned sB32 = (unsigned)__cvta_generic_to_shared(sB);

    __half* yout = ISG ? d_yg    : d_yx;
    float*  ssum = ISG ? d_sum_g : d_sum_x;
    float*  ssq  = ISG ? d_sq_g  : d_sq_x;

    const int tid  = threadIdx.x;
    const int warp = tid >> 5, lane = tid & 31;
    const int wm = warp >> 2, wn = warp & 3;
    const int n  = blockIdx.y;
    const int p0 = blockIdx.x * 128;
    const float* srcn = src + (size_t)n * K * S + p0;

    // stage all of W (fp32->fp16, xor-swizzled 16B chunks)
    constexpr int CHR = K / 8;
    for (int idx = tid; idx < 128 * CHR; idx += 256) {
        int r = idx / CHR, k16 = idx % CHR;
        const float4* wp = reinterpret_cast<const float4*>(W + r * K + k16 * 8);
        float4 w0 = wp[0], w1 = wp[1];
        uint4 u;
        u.x = pack2h(w0.x, w0.y); u.y = pack2h(w0.z, w0.w);
        u.z = pack2h(w1.x, w1.y); u.w = pack2h(w1.z, w1.w);
        int phys = (k16 & ~7) | ((k16 & 7) ^ (r & 7));
        *reinterpret_cast<uint4*>(sA + r * K + phys * 8) = u;
    }

    float acc[4][4][4];
#pragma unroll
    for (int a = 0; a < 4; a++)
#pragma unroll
        for (int b = 0; b < 4; b++)
#pragma unroll
            for (int c = 0; c < 4; c++) acc[a][b][c] = 0.f;

    const int pst = tid & 127;          // staging point
    const int jh  = tid >> 7;           // staging 16-chan half (0/1)
    constexpr int NIT = K / KC;

    float v[16];
    // prefetch tile 0
    {
        const float* base = srcn + (size_t)(jh * 16) * S + pst;
#pragma unroll
        for (int e = 0; e < 16; e++) v[e] = base[(size_t)e * S];
    }

    for (int it = 0; it < NIT; it++) {
        // convert+store regs -> sB[it&1]
        {
            __half* sb = sB + (it & 1) * (128 * SBROW);
            uint4 u0, u1;
            u0.x = pack2h(v[0], v[1]);  u0.y = pack2h(v[2], v[3]);
            u0.z = pack2h(v[4], v[5]);  u0.w = pack2h(v[6], v[7]);
            u1.x = pack2h(v[8], v[9]);  u1.y = pack2h(v[10], v[11]);
            u1.z = pack2h(v[12], v[13]);u1.w = pack2h(v[14], v[15]);
            *reinterpret_cast<uint4*>(sb + pst * SBROW + (2 * jh) * 8)     = u0;
            *reinterpret_cast<uint4*>(sb + pst * SBROW + (2 * jh + 1) * 8) = u1;
        }
        __syncthreads();
        // prefetch tile it+1 (LDGs in flight across the MMA block)
        if (it + 1 < NIT) {
            const float* base = srcn + (size_t)((it + 1) * KC + jh * 16) * S + pst;
#pragma unroll
            for (int e = 0; e < 16; e++) v[e] = base[(size_t)e * S];
        }
        // MMA on sB[it&1]
        const unsigned sbb = sB32 + (unsigned)((it & 1) * (128 * SBROW) * 2);
        const int c0 = it * KC;
#pragma unroll
        for (int ks = 0; ks < 2; ks++) {
            unsigned afr[4][4];
#pragma unroll
            for (int tm = 0; tm < 4; tm++) {
                int row = wm * 64 + tm * 16 + (lane & 15);
                int kch = (c0 >> 3) + ks * 2 + (lane >> 4);
                int phys = (kch & ~7) | ((kch & 7) ^ (row & 7));
                ldsm_x4(afr[tm], sA32 + (unsigned)(row * K * 2 + phys * 16));
            }
            unsigned bfr[4][2];
#pragma unroll
            for (int tp = 0; tp < 2; tp++) {
                int p = wn * 32 + tp * 16 + ((lane >> 4) * 8) + (lane & 7);
                int kch = ks * 2 + ((lane >> 3) & 1);
                unsigned r4[4];
                ldsm_x4(r4, sbb + (unsigned)((p * SBROW + kch * 8) * 2));
                bfr[tp * 2][0] = r4[0];     bfr[tp * 2][1] = r4[1];
                bfr[tp * 2 + 1][0] = r4[2]; bfr[tp * 2 + 1][1] = r4[3];
            }
#pragma unroll
            for (int tm = 0; tm < 4; tm++)
#pragma unroll
                for (int tn = 0; tn < 4; tn++)
                    mma16816(acc[tm][tn], afr[tm], bfr[tn]);
        }
    }

    // epilogue: fp16 store + per-i stats from fp32 accumulators
    __half* yn = yout + (size_t)n * I * S + p0;
#pragma unroll
    for (int tm = 0; tm < 4; tm++) {
        int r1 = wm * 64 + tm * 16 + (lane >> 2);
        float s1 = 0.f, q1 = 0.f, s2 = 0.f, q2 = 0.f;
#pragma unroll
        for (int tn = 0; tn < 4; tn++) {
            float* c = acc[tm][tn];
            int col = wn * 32 + tn * 8 + (lane & 3) * 2;
            *reinterpret_cast<__half2*>(yn + (size_t)r1 * S + col) =
                __floats2half2_rn(c[0], c[1]);
            *reinterpret_cast<__half2*>(yn + (size_t)(r1 + 8) * S + col) =
                __floats2half2_rn(c[2], c[3]);
            s1 += c[0] + c[1]; q1 += c[0] * c[0] + c[1] * c[1];
            s2 += c[2] + c[3]; q2 += c[2] * c[2] + c[3] * c[3];
        }
#pragma unroll
        for (int off = 2; off > 0; off >>= 1) {
            s1 += __shfl_down_sync(0xFFFFFFFFu, s1, off, 4);
            q1 += __shfl_down_sync(0xFFFFFFFFu, q1, off, 4);
            s2 += __shfl_down_sync(0xFFFFFFFFu, s2, off, 4);
            q2 += __shfl_down_sync(0xFFFFFFFFu, q2, off, 4);
        }
        if ((lane & 3) == 0) {
            atomicAdd(&ssum[n * I + r1], s1);
            atomicAdd(&ssq [n * I + r1], q1);
            atomicAdd(&ssum[n * I + r1 + 8], s2);
            atomicAdd(&ssq [n * I + r1 + 8], q2);
        }
    }
}

// ---- coefs ------------------------------------------------------------------
__global__ void k_coefs(const float* __restrict__ gam_g, const float* __restrict__ bet_g,
                        const float* __restrict__ gam_x, const float* __restrict__ bet_x) {
    int t = threadIdx.x;
    if (t < NB * I) {
        int i = t & (I - 1);
        const float inv = 1.f / (float)S;
        float m   = d_sum_g[t] * inv;
        float var = fmaxf(d_sq_g[t] * inv - m * m, 0.f);
        float A   = gam_g[i] * rsqrtf(var + EPS);
        d_cAg[t] = A; d_cBg[t] = bet_g[i] - m * A;
        m   = d_sum_x[t] * inv;
        var = fmaxf(d_sq_x[t] * inv - m * m, 0.f);
        A   = gam_x[i] * rsqrtf(var + EPS);
        d_cAx[t] = A; d_cBx[t] = bet_x[i] - m * A;
    }
}

// ---- combine: z = Wpsi . relu(Ag*yg+Bg + Ax*yx+Bx), + z stats ---------------
// grid (S/1024, NB); thread handles 4 points (uint2 per tensor per i).
__global__ void __launch_bounds__(256) k_combine(const float* __restrict__ Wpsi) {
    __shared__ float sc[5 * I];
    const int tid = threadIdx.x;
    const int n   = blockIdx.y;
    const int p0  = blockIdx.x * 1024;
    if (tid < I) {
        sc[tid]         = d_cAg[n * I + tid];
        sc[I + tid]     = d_cBg[n * I + tid];
        sc[2 * I + tid] = d_cAx[n * I + tid];
        sc[3 * I + tid] = d_cBx[n * I + tid];
        sc[4 * I + tid] = Wpsi[tid];
    }
    __syncthreads();
    const __half* ygb = d_yg + (size_t)n * I * S + p0 + tid * 4;
    const __half* yxb = d_yx + (size_t)n * I * S + p0 + tid * 4;
    float za[4] = {0.f, 0.f, 0.f, 0.f};

#pragma unroll 4
    for (int i = 0; i < I; i++) {
        uint2 ua = *reinterpret_cast<const uint2*>(ygb + (size_t)i * S);
        uint2 ub = *reinterpret_cast<const uint2*>(yxb + (size_t)i * S);
        float Ag = sc[i], Ax = sc[2 * I + i];
        float C  = sc[I + i] + sc[3 * I + i];
        float w  = sc[4 * I + i];
        H2U a0, a1, b0, b1;
        a0.u = ua.x; a1.u = ua.y; b0.u = ub.x; b1.u = ub.y;
        float2 fa0 = __half22float2(a0.h), fa1 = __half22float2(a1.h);
        float2 fb0 = __half22float2(b0.h), fb1 = __half22float2(b1.h);
        za[0] += w * fmaxf(fmaf(Ag, fa0.x, fmaf(Ax, fb0.x, C)), 0.f);
        za[1] += w * fmaxf(fmaf(Ag, fa0.y, fmaf(Ax, fb0.y, C)), 0.f);
        za[2] += w * fmaxf(fmaf(Ag, fa1.x, fmaf(Ax, fb1.x, C)), 0.f);
        za[3] += w * fmaxf(fmaf(Ag, fa1.y, fmaf(Ax, fb1.y, C)), 0.f);
    }
    *reinterpret_cast<float4*>(&d_z[n * S + p0 + tid * 4]) =
        make_float4(za[0], za[1], za[2], za[3]);

    float s = za[0] + za[1] + za[2] + za[3];
    float q = za[0]*za[0] + za[1]*za[1] + za[2]*za[2] + za[3]*za[3];
#pragma unroll
    for (int off = 16; off > 0; off >>= 1) {
        s += __shfl_down_sync(0xFFFFFFFFu, s, off);
        q += __shfl_down_sync(0xFFFFFFFFu, q, off);
    }
    __shared__ float rs[8], rq[8];
    int wid = tid >> 5, ln = tid & 31;
    if (ln == 0) { rs[wid] = s; rq[wid] = q; }
    __syncthreads();
    if (tid == 0) {
        float st = 0.f, qt = 0.f;
#pragma unroll
        for (int w2 = 0; w2 < 8; w2++) { st += rs[w2]; qt += rq[w2]; }
        atomicAdd(&d_zstat[n], st);
        atomicAdd(&d_zstat[NB + n], qt);
    }
}

// ---- fused alpha+mul: out = x * sigmoid(A*z+B) ------------------------------
__global__ void k_mul(const float* __restrict__ x, float* __restrict__ out,
                      const float* __restrict__ gam_p, const float* __restrict__ bet_p) {
    const int idx = blockIdx.x * blockDim.x + threadIdx.x;   // float4 index
    const int n   = idx >> 22;
    const int p4  = idx & (S / 4 - 1);
    const float inv = 1.f / (float)S;
    float m   = d_zstat[n] * inv;
    float var = fmaxf(d_zstat[NB + n] * inv - m * m, 0.f);
    float A   = gam_p[0] * rsqrtf(var + EPS);
    float B   = bet_p[0] - m * A;
    float4 z  = *reinterpret_cast<const float4*>(&d_z[n * S + p4 * 4]);
    float4 xv = reinterpret_cast<const float4*>(x)[idx];
    float4 o;
    o.x = xv.x / (1.f + __expf(-fmaf(A, z.x, B)));
    o.y = xv.y / (1.f + __expf(-fmaf(A, z.y, B)));
    o.z = xv.z / (1.f + __expf(-fmaf(A, z.z, B)));
    o.w = xv.w / (1.f + __expf(-fmaf(A, z.w, B)));
    reinterpret_cast<float4*>(out)[idx] = o;
}

// ============================================================================
extern "C" void kernel_launch(void* const* d_in, const int* in_sizes, int n_in,
                              void* d_out, int out_size) {
    const float* g     = (const float*)d_in[0];
    const float* x     = (const float*)d_in[1];
    const float* Wg    = (const float*)d_in[2];
    const float* Wx    = (const float*)d_in[3];
    const float* Wpsi  = (const float*)d_in[4];
    const float* gam_g = (const float*)d_in[5];
    const float* bet_g = (const float*)d_in[6];
    const float* gam_x = (const float*)d_in[7];
    const float* bet_x = (const float*)d_in[8];
    const float* gam_p = (const float*)d_in[9];
    const float* bet_p = (const float*)d_in[10];
    float* out = (float*)d_out;

    const int SMEM_G = 128 * G  * 2 + 2 * 128 * SBROW * 2;   // 85504
    const int SMEM_X = 128 * XC * 2 + 2 * 128 * SBROW * 2;   // 53248
    cudaFuncSetAttribute(k_gemm<G,  true >,
                         cudaFuncAttributeMaxDynamicSharedMemorySize, SMEM_G);
    cudaFuncSetAttribute(k_gemm<XC, false>,
                         cudaFuncAttributeMaxDynamicSharedMemorySize, SMEM_X);

    dim3 ggrid(S / 128, NB);

    // launch order chosen so k_gemm_g is launch #4 (ncu capture slot)
    k_zero<<<1, 256>>>();
    k_gemm<XC, false><<<ggrid, 256, SMEM_X>>>(x, Wx);
    k_zero2<<<1, 32>>>();
    k_gemm<G,  true ><<<ggrid, 256, SMEM_G>>>(g, Wg);

    k_coefs<<<1, 256>>>(gam_g, bet_g, gam_x, bet_x);

    dim3 cgrid(S / 1024, NB);                      // 128 x 2
    k_combine<<<cgrid, 256>>>(Wpsi);

    int total4 = NB * XC * S / 4;                  // 16,777,216 float4
    k_mul<<<total4 / 256, 256>>>(x, out, gam_p, bet_p);
}

// round 4
// speedup vs baseline: 2.8481x; 1.0831x over previous
#include <cuda_runtime.h>
#include <cuda_fp16.h>

// ============================================================================
// AttentionGate3D — round 4: transposed-staging HMMA GEMM (ldsm.trans B path,
// LDG.128 loads, 2-deep register prefetch), pre-converted fp16 weights.
// ============================================================================

#define EPS 1e-5f

constexpr int NB = 2;
constexpr int G  = 256;
constexpr int XC = 128;
constexpr int I  = 128;
constexpr int S  = 32 * 64 * 64;   // 131072

// ---- scratch ----
__device__ __half d_yg[NB * I * S];
__device__ __half d_yx[NB * I * S];
__device__ __half d_whg[I * G];
__device__ __half d_whx[I * XC];
__device__ float  d_z[NB * S];
__device__ float  d_sum_g[NB * I];
__device__ float  d_sq_g [NB * I];
__device__ float  d_sum_x[NB * I];
__device__ float  d_sq_x [NB * I];
__device__ float  d_zstat[2 * NB];
__device__ float  d_cAg[NB * I], d_cBg[NB * I];
__device__ float  d_cAx[NB * I], d_cBx[NB * I];

// ---- W fp32->fp16 pre-convert + stat zeroing ----
__global__ void k_wconv(const float* __restrict__ Wg, const float* __restrict__ Wx) {
    int t = blockIdx.x * 256 + threadIdx.x;
    if (t < I * G)  d_whg[t] = __float2half_rn(Wg[t]);
    if (t < I * XC) d_whx[t] = __float2half_rn(Wx[t]);
    if (t < NB * I) {
        d_sum_g[t] = 0.f; d_sq_g[t] = 0.f;
        d_sum_x[t] = 0.f; d_sq_x[t] = 0.f;
    }
}
__global__ void k_zero2() {
    int t = threadIdx.x;
    if (t < 2 * NB) d_zstat[t] = 0.f;
}

// ---- MMA helpers ----
__device__ __forceinline__ void ldsm_x4(unsigned (&r)[4], unsigned addr) {
    asm volatile("ldmatrix.sync.aligned.m8n8.x4.shared.b16 {%0,%1,%2,%3}, [%4];"
        : "=r"(r[0]), "=r"(r[1]), "=r"(r[2]), "=r"(r[3]) : "r"(addr));
}
__device__ __forceinline__ void ldsm_x4_t(unsigned (&r)[4], unsigned addr) {
    asm volatile("ldmatrix.sync.aligned.m8n8.x4.trans.shared.b16 {%0,%1,%2,%3}, [%4];"
        : "=r"(r[0]), "=r"(r[1]), "=r"(r[2]), "=r"(r[3]) : "r"(addr));
}
__device__ __forceinline__ void mma16816(float (&d)[4], const unsigned (&a)[4],
                                         const unsigned (&b)[2]) {
    asm volatile("mma.sync.aligned.m16n8k16.row.col.f32.f16.f16.f32 "
        "{%0,%1,%2,%3}, {%4,%5,%6,%7}, {%8,%9}, {%0,%1,%2,%3};"
        : "+f"(d[0]), "+f"(d[1]), "+f"(d[2]), "+f"(d[3])
        : "r"(a[0]), "r"(a[1]), "r"(a[2]), "r"(a[3]), "r"(b[0]), "r"(b[1]));
}
union H2U { __half2 h; unsigned u; };
__device__ __forceinline__ unsigned pack2h(float a, float b) {
    H2U v; v.h = __floats2half2_rn(a, b); return v.u;
}

// ---- GEMM: y[n,i,p] = sum_c W[i,c]*src[n,c,p] ------------------------------
// CTA tile M=128(i) x N=128(p); 8 warps = 2(M) x 4(N), warp 64M x 32N.
// K in KC=16 chunks; sB[c][p] fp16 (16 rows x 128 halves) double-buffered,
// loads prefetched 2 chunks ahead into registers (float4 x2 per thread).
template<int K, bool ISG>
__global__ void __launch_bounds__(256, 2) k_gemm(const float* __restrict__ src) {
    extern __shared__ __align__(16) char smem[];
    __half* sA = reinterpret_cast<__half*>(smem);              // 128*K halves
    __half* sB = reinterpret_cast<__half*>(smem) + 128 * K;    // 2*2048 halves
    const unsigned sA32 = (unsigned)__cvta_generic_to_shared(sA);
    const unsigned sB32 = (unsigned)__cvta_generic_to_shared(sB);

    const __half* wh  = ISG ? d_whg   : d_whx;
    __half* yout = ISG ? d_yg    : d_yx;
    float*  ssum = ISG ? d_sum_g : d_sum_x;
    float*  ssq  = ISG ? d_sq_g  : d_sq_x;

    const int tid  = threadIdx.x;
    const int warp = tid >> 5, lane = tid & 31;
    const int wm = warp >> 2, wn = warp & 3;
    const int n  = blockIdx.y;
    const int p0 = blockIdx.x * 128;
    const float* srcn = src + (size_t)n * K * S + p0;

    // stage all of W (already fp16), xor-swizzled 16B chunks
    constexpr int CHR = K / 8;
    for (int idx = tid; idx < 128 * CHR; idx += 256) {
        int r = idx / CHR, k16 = idx % CHR;
        uint4 u = reinterpret_cast<const uint4*>(wh + r * K)[k16];
        int phys = (k16 & ~7) | ((k16 & 7) ^ (r & 7));
        *reinterpret_cast<uint4*>(sA + r * K + phys * 8) = u;
    }

    float acc[4][4][4] = {};

    // staging role: channel cst (0..15), point-block pb (0..15, 4 pts each)
    const int cst = tid >> 4;
    const int pb  = tid & 15;

    auto ldtile = [&](float4 (&v)[2], int it) {
        const float* b = srcn + (size_t)(it * 16 + cst) * S + pb * 4;
        v[0] = *reinterpret_cast<const float4*>(b);
        v[1] = *reinterpret_cast<const float4*>(b + 64);
    };

    float4 v0[2], v1[2];
    ldtile(v0, 0);
    ldtile(v1, 1);

    // STS byte offsets within a stage (swizzled, conflict-free)
    const int swz  = ((pb >> 1) ^ (cst & 7));
    const int sts0 = (cst * 128 + (swz << 3)       + ((pb & 1) << 2)) * 2;
    const int sts1 = (cst * 128 + ((8 + swz) << 3) + ((pb & 1) << 2)) * 2;

    constexpr int NIT = K / 16;

    auto step = [&](float4 (&v)[2], int it) {
        __half* sb = sB + (it & 1) * 2048;
        uint2 u0, u1;
        u0.x = pack2h(v[0].x, v[0].y); u0.y = pack2h(v[0].z, v[0].w);
        u1.x = pack2h(v[1].x, v[1].y); u1.y = pack2h(v[1].z, v[1].w);
        *reinterpret_cast<uint2*>(reinterpret_cast<char*>(sb) + sts0) = u0;
        *reinterpret_cast<uint2*>(reinterpret_cast<char*>(sb) + sts1) = u1;
        __syncthreads();
        if (it + 2 < NIT) ldtile(v, it + 2);   // LDGs 2 chunks ahead

        const unsigned sbb = sB32 + (unsigned)((it & 1) * 4096);
        unsigned afr[4][4];
#pragma unroll
        for (int tm = 0; tm < 4; tm++) {
            int row = wm * 64 + tm * 16 + (lane & 15);
            int kch = it * 2 + (lane >> 4);
            int phys = (kch & ~7) | ((kch & 7) ^ (row & 7));
            ldsm_x4(afr[tm], sA32 + (unsigned)(row * K * 2 + phys * 16));
        }
        unsigned bfr[4][2];
#pragma unroll
        for (int h = 0; h < 2; h++) {
            int nbX  = 2 * h + ((lane >> 4) & 1);          // n-block per half
            int c    = ((lane >> 3) & 1) * 8 + (lane & 7); // k row 0..15
            int phys = (wn * 4 + nbX) ^ (lane & 7);
            unsigned r4[4];
            ldsm_x4_t(r4, sbb + (unsigned)((c * 128 + phys * 8) * 2));
            bfr[2 * h][0]     = r4[0]; bfr[2 * h][1]     = r4[1];
            bfr[2 * h + 1][0] = r4[2]; bfr[2 * h + 1][1] = r4[3];
        }
#pragma unroll
        for (int tm = 0; tm < 4; tm++)
#pragma unroll
            for (int tn = 0; tn < 4; tn++)
                mma16816(acc[tm][tn], afr[tm], bfr[tn]);
    };

#pragma unroll
    for (int it = 0; it < NIT; it += 2) {
        step(v0, it);
        step(v1, it + 1);
    }

    // epilogue: fp16 store + per-i stats from fp32 accumulators
    __half* yn = yout + (size_t)n * I * S + p0;
#pragma unroll
    for (int tm = 0; tm < 4; tm++) {
        int r1 = wm * 64 + tm * 16 + (lane >> 2);
        float s1 = 0.f, q1 = 0.f, s2 = 0.f, q2 = 0.f;
#pragma unroll
        for (int tn = 0; tn < 4; tn++) {
            float* c = acc[tm][tn];
            int col = wn * 32 + tn * 8 + (lane & 3) * 2;
            *reinterpret_cast<__half2*>(yn + (size_t)r1 * S + col) =
                __floats2half2_rn(c[0], c[1]);
            *reinterpret_cast<__half2*>(yn + (size_t)(r1 + 8) * S + col) =
                __floats2half2_rn(c[2], c[3]);
            s1 += c[0] + c[1]; q1 += c[0] * c[0] + c[1] * c[1];
            s2 += c[2] + c[3]; q2 += c[2] * c[2] + c[3] * c[3];
        }
#pragma unroll
        for (int off = 2; off > 0; off >>= 1) {
            s1 += __shfl_down_sync(0xFFFFFFFFu, s1, off, 4);
            q1 += __shfl_down_sync(0xFFFFFFFFu, q1, off, 4);
            s2 += __shfl_down_sync(0xFFFFFFFFu, s2, off, 4);
            q2 += __shfl_down_sync(0xFFFFFFFFu, q2, off, 4);
        }
        if ((lane & 3) == 0) {
            atomicAdd(&ssum[n * I + r1], s1);
            atomicAdd(&ssq [n * I + r1], q1);
            atomicAdd(&ssum[n * I + r1 + 8], s2);
            atomicAdd(&ssq [n * I + r1 + 8], q2);
        }
    }
}

// ---- coefs ------------------------------------------------------------------
__global__ void k_coefs(const float* __restrict__ gam_g, const float* __restrict__ bet_g,
                        const float* __restrict__ gam_x, const float* __restrict__ bet_x) {
    int t = threadIdx.x;
    if (t < NB * I) {
        int i = t & (I - 1);
        const float inv = 1.f / (float)S;
        float m   = d_sum_g[t] * inv;
        float var = fmaxf(d_sq_g[t] * inv - m * m, 0.f);
        float A   = gam_g[i] * rsqrtf(var + EPS);
        d_cAg[t] = A; d_cBg[t] = bet_g[i] - m * A;
        m   = d_sum_x[t] * inv;
        var = fmaxf(d_sq_x[t] * inv - m * m, 0.f);
        A   = gam_x[i] * rsqrtf(var + EPS);
        d_cAx[t] = A; d_cBx[t] = bet_x[i] - m * A;
    }
}

// ---- combine: z = Wpsi . relu(Ag*yg+Bg + Ax*yx+Bx), + z stats ---------------
__global__ void __launch_bounds__(256) k_combine(const float* __restrict__ Wpsi) {
    __shared__ float sc[5 * I];
    const int tid = threadIdx.x;
    const int n   = blockIdx.y;
    const int p0  = blockIdx.x * 1024;
    if (tid < I) {
        sc[tid]         = d_cAg[n * I + tid];
        sc[I + tid]     = d_cBg[n * I + tid];
        sc[2 * I + tid] = d_cAx[n * I + tid];
        sc[3 * I + tid] = d_cBx[n * I + tid];
        sc[4 * I + tid] = Wpsi[tid];
    }
    __syncthreads();
    const __half* ygb = d_yg + (size_t)n * I * S + p0 + tid * 4;
    const __half* yxb = d_yx + (size_t)n * I * S + p0 + tid * 4;
    float za[4] = {0.f, 0.f, 0.f, 0.f};

#pragma unroll 4
    for (int i = 0; i < I; i++) {
        uint2 ua = *reinterpret_cast<const uint2*>(ygb + (size_t)i * S);
        uint2 ub = *reinterpret_cast<const uint2*>(yxb + (size_t)i * S);
        float Ag = sc[i], Ax = sc[2 * I + i];
        float C  = sc[I + i] + sc[3 * I + i];
        float w  = sc[4 * I + i];
        H2U a0, a1, b0, b1;
        a0.u = ua.x; a1.u = ua.y; b0.u = ub.x; b1.u = ub.y;
        float2 fa0 = __half22float2(a0.h), fa1 = __half22float2(a1.h);
        float2 fb0 = __half22float2(b0.h), fb1 = __half22float2(b1.h);
        za[0] += w * fmaxf(fmaf(Ag, fa0.x, fmaf(Ax, fb0.x, C)), 0.f);
        za[1] += w * fmaxf(fmaf(Ag, fa0.y, fmaf(Ax, fb0.y, C)), 0.f);
        za[2] += w * fmaxf(fmaf(Ag, fa1.x, fmaf(Ax, fb1.x, C)), 0.f);
        za[3] += w * fmaxf(fmaf(Ag, fa1.y, fmaf(Ax, fb1.y, C)), 0.f);
    }
    *reinterpret_cast<float4*>(&d_z[n * S + p0 + tid * 4]) =
        make_float4(za[0], za[1], za[2], za[3]);

    float s = za[0] + za[1] + za[2] + za[3];
    float q = za[0]*za[0] + za[1]*za[1] + za[2]*za[2] + za[3]*za[3];
#pragma unroll
    for (int off = 16; off > 0; off >>= 1) {
        s += __shfl_down_sync(0xFFFFFFFFu, s, off);
        q += __shfl_down_sync(0xFFFFFFFFu, q, off);
    }
    __shared__ float rs[8], rq[8];
    int wid = tid >> 5, ln = tid & 31;
    if (ln == 0) { rs[wid] = s; rq[wid] = q; }
    __syncthreads();
    if (tid == 0) {
        float st = 0.f, qt = 0.f;
#pragma unroll
        for (int w2 = 0; w2 < 8; w2++) { st += rs[w2]; qt += rq[w2]; }
        atomicAdd(&d_zstat[n], st);
        atomicAdd(&d_zstat[NB + n], qt);
    }
}

// ---- fused alpha+mul: out = x * sigmoid(A*z+B) ------------------------------
__global__ void k_mul(const float* __restrict__ x, float* __restrict__ out,
                      const float* __restrict__ gam_p, const float* __restrict__ bet_p) {
    const int idx = blockIdx.x * blockDim.x + threadIdx.x;   // float4 index
    const int n   = idx >> 22;
    const int p4  = idx & (S / 4 - 1);
    const float inv = 1.f / (float)S;
    float m   = d_zstat[n] * inv;
    float var = fmaxf(d_zstat[NB + n] * inv - m * m, 0.f);
    float A   = gam_p[0] * rsqrtf(var + EPS);
    float B   = bet_p[0] - m * A;
    float4 z  = *reinterpret_cast<const float4*>(&d_z[n * S + p4 * 4]);
    float4 xv = reinterpret_cast<const float4*>(x)[idx];
    float4 o;
    o.x = xv.x / (1.f + __expf(-fmaf(A, z.x, B)));
    o.y = xv.y / (1.f + __expf(-fmaf(A, z.y, B)));
    o.z = xv.z / (1.f + __expf(-fmaf(A, z.z, B)));
    o.w = xv.w / (1.f + __expf(-fmaf(A, z.w, B)));
    reinterpret_cast<float4*>(out)[idx] = o;
}

// ============================================================================
extern "C" void kernel_launch(void* const* d_in, const int* in_sizes, int n_in,
                              void* d_out, int out_size) {
    const float* g     = (const float*)d_in[0];
    const float* x     = (const float*)d_in[1];
    const float* Wg    = (const float*)d_in[2];
    const float* Wx    = (const float*)d_in[3];
    const float* Wpsi  = (const float*)d_in[4];
    const float* gam_g = (const float*)d_in[5];
    const float* bet_g = (const float*)d_in[6];
    const float* gam_x = (const float*)d_in[7];
    const float* bet_x = (const float*)d_in[8];
    const float* gam_p = (const float*)d_in[9];
    const float* bet_p = (const float*)d_in[10];
    float* out = (float*)d_out;

    const int SMEM_G = 128 * G  * 2 + 2 * 4096;   // 73728
    const int SMEM_X = 128 * XC * 2 + 2 * 4096;   // 40960
    cudaFuncSetAttribute(k_gemm<G,  true >,
                         cudaFuncAttributeMaxDynamicSharedMemorySize, SMEM_G);
    cudaFuncSetAttribute(k_gemm<XC, false>,
                         cudaFuncAttributeMaxDynamicSharedMemorySize, SMEM_X);

    dim3 ggrid(S / 128, NB);                       // 1024 x 2

    // order keeps k_gemm<G> at launch slot 4 (ncu capture)
    k_wconv<<<128, 256>>>(Wg, Wx);
    k_gemm<XC, false><<<ggrid, 256, SMEM_X>>>(x);
    k_zero2<<<1, 32>>>();
    k_gemm<G,  true ><<<ggrid, 256, SMEM_G>>>(g);

    k_coefs<<<1, 256>>>(gam_g, bet_g, gam_x, bet_x);

    dim3 cgrid(S / 1024, NB);                      // 128 x 2
    k_combine<<<cgrid, 256>>>(Wpsi);

    int total4 = NB * XC * S / 4;                  // 16,777,216 float4
    k_mul<<<total4 / 256, 256>>>(x, out, gam_p, bet_p);
}

// round 5
// speedup vs baseline: 2.9431x; 1.0334x over previous
#include <cuda_runtime.h>
#include <cuda_fp16.h>

// ============================================================================
// AttentionGate3D — round 5: cp.async-pipelined HMMA GEMM.
// fp32 B tiles stream through a 4-stage per-thread cp.async FIFO (no barriers
// needed on the fp32 staging), converted to swizzled fp16 smem, one
// __syncthreads per K-chunk, ldsm/ldsm.trans + mma.m16n8k16.
// ============================================================================

#define EPS 1e-5f

constexpr int NB = 2;
constexpr int G  = 256;
constexpr int XC = 128;
constexpr int I  = 128;
constexpr int S  = 32 * 64 * 64;   // 131072
constexpr int STAGES = 4;          // cp.async fp32 stages (8KB each)

// ---- scratch ----
__device__ __half d_yg[NB * I * S];
__device__ __half d_yx[NB * I * S];
__device__ __half d_whg[I * G];
__device__ __half d_whx[I * XC];
__device__ float  d_z[NB * S];
__device__ float  d_sum_g[NB * I];
__device__ float  d_sq_g [NB * I];
__device__ float  d_sum_x[NB * I];
__device__ float  d_sq_x [NB * I];
__device__ float  d_zstat[2 * NB];
__device__ float  d_cAg[NB * I], d_cBg[NB * I];
__device__ float  d_cAx[NB * I], d_cBx[NB * I];

// ---- W fp32->fp16 pre-convert + stat zeroing ----
__global__ void k_wconv(const float* __restrict__ Wg, const float* __restrict__ Wx) {
    int t = blockIdx.x * 256 + threadIdx.x;
    if (t < I * G)  d_whg[t] = __float2half_rn(Wg[t]);
    if (t < I * XC) d_whx[t] = __float2half_rn(Wx[t]);
    if (t < NB * I) {
        d_sum_g[t] = 0.f; d_sq_g[t] = 0.f;
        d_sum_x[t] = 0.f; d_sq_x[t] = 0.f;
    }
}
__global__ void k_zero2() {
    int t = threadIdx.x;
    if (t < 2 * NB) d_zstat[t] = 0.f;
}

// ---- MMA helpers ----
__device__ __forceinline__ void ldsm_x4(unsigned (&r)[4], unsigned addr) {
    asm volatile("ldmatrix.sync.aligned.m8n8.x4.shared.b16 {%0,%1,%2,%3}, [%4];"
        : "=r"(r[0]), "=r"(r[1]), "=r"(r[2]), "=r"(r[3]) : "r"(addr));
}
__device__ __forceinline__ void ldsm_x4_t(unsigned (&r)[4], unsigned addr) {
    asm volatile("ldmatrix.sync.aligned.m8n8.x4.trans.shared.b16 {%0,%1,%2,%3}, [%4];"
        : "=r"(r[0]), "=r"(r[1]), "=r"(r[2]), "=r"(r[3]) : "r"(addr));
}
__device__ __forceinline__ void mma16816(float (&d)[4], const unsigned (&a)[4],
                                         const unsigned (&b)[2]) {
    asm volatile("mma.sync.aligned.m16n8k16.row.col.f32.f16.f16.f32 "
        "{%0,%1,%2,%3}, {%4,%5,%6,%7}, {%8,%9}, {%0,%1,%2,%3};"
        : "+f"(d[0]), "+f"(d[1]), "+f"(d[2]), "+f"(d[3])
        : "r"(a[0]), "r"(a[1]), "r"(a[2]), "r"(a[3]), "r"(b[0]), "r"(b[1]));
}
union H2U { __half2 h; unsigned u; };
__device__ __forceinline__ unsigned pack2h(float a, float b) {
    H2U v; v.h = __floats2half2_rn(a, b); return v.u;
}
__device__ __forceinline__ void cp16(unsigned dst, const float* src) {
    asm volatile("cp.async.cg.shared.global [%0], [%1], 16;" :: "r"(dst), "l"(src));
}
__device__ __forceinline__ void cp_commit() {
    asm volatile("cp.async.commit_group;" ::: "memory");
}
template<int N>
__device__ __forceinline__ void cp_wait() {
    asm volatile("cp.async.wait_group %0;" :: "n"(N) : "memory");
}

// ---- GEMM: y[n,i,p] = sum_c W[i,c]*src[n,c,p] ------------------------------
// CTA tile M=128(i) x N=128(p); 8 warps = 2(M) x 4(N), warp 64M x 32N.
// K in 16-chunks. fp32 src -> 4-stage cp.async FIFO (per-thread private) ->
// cvt -> swizzled fp16 sBh (double buffer) -> ldsm.trans -> MMA.
template<int K, bool ISG>
__global__ void __launch_bounds__(256, 2) k_gemm(const float* __restrict__ src) {
    constexpr int NIT = K / 16;
    extern __shared__ __align__(16) char smem[];
    __half* sA  = reinterpret_cast<__half*>(smem);                  // 128*K halves
    float*  sS  = reinterpret_cast<float*>(smem + 128 * K * 2);     // STAGES*2048 fl
    __half* sBh = reinterpret_cast<__half*>(smem + 128 * K * 2 + STAGES * 8192);
    const unsigned sA32  = (unsigned)__cvta_generic_to_shared(sA);
    const unsigned sS32  = (unsigned)__cvta_generic_to_shared(sS);
    const unsigned sBh32 = (unsigned)__cvta_generic_to_shared(sBh);

    const __half* wh  = ISG ? d_whg   : d_whx;
    __half* yout = ISG ? d_yg    : d_yx;
    float*  ssum = ISG ? d_sum_g : d_sum_x;
    float*  ssq  = ISG ? d_sq_g  : d_sq_x;

    const int tid  = threadIdx.x;
    const int warp = tid >> 5, lane = tid & 31;
    const int wm = warp >> 2, wn = warp & 3;
    const int n  = blockIdx.y;
    const int p0 = blockIdx.x * 128;
    const float* srcn = src + (size_t)n * K * S + p0;

    // staging role: channel cst (0..15), point-block pb (0..15, 8 pts each)
    const int cst = tid >> 4;
    const int pb  = tid & 15;
    const float* gp = srcn + (size_t)cst * S + pb * 4;
    const unsigned myoff = (unsigned)((cst * 128 + pb * 4) * 4);   // bytes

    auto issue = [&](int it) {
        unsigned dst = sS32 + (unsigned)((it % STAGES) * 8192) + myoff;
        const float* s0 = gp + (size_t)it * 16 * S;
        cp16(dst, s0);
        cp16(dst + 256, s0 + 64);
    };

    // prologue: fill STAGES-1 stages
    issue(0); cp_commit();
    issue(1); cp_commit();
    issue(2); cp_commit();

    // stage all of W (already fp16), xor-swizzled 16B chunks
    constexpr int CHR = K / 8;
    for (int idx = tid; idx < 128 * CHR; idx += 256) {
        int r = idx / CHR, k16 = idx % CHR;
        uint4 u = reinterpret_cast<const uint4*>(wh + r * K)[k16];
        int phys = (k16 & ~7) | ((k16 & 7) ^ (r & 7));
        *reinterpret_cast<uint4*>(sA + r * K + phys * 8) = u;
    }

    float acc[4][4][4] = {};

    // fp16 STS byte offsets within a stage (swizzled, conflict-free)
    const int swz  = ((pb >> 1) ^ (cst & 7));
    const int sts0 = (cst * 128 + (swz << 3)       + ((pb & 1) << 2)) * 2;
    const int sts1 = (cst * 128 + ((8 + swz) << 3) + ((pb & 1) << 2)) * 2;

    for (int it = 0; it < NIT; it++) {
        cp_wait<STAGES - 2>();          // this thread's stage `it` landed
        const float4* rp = reinterpret_cast<const float4*>(
            sS + (it % STAGES) * 2048 + cst * 128 + pb * 4);
        float4 w0 = rp[0];
        float4 w1 = rp[16];             // +64 floats

        __half* sb = sBh + (it & 1) * 2048;
        uint2 u0, u1;
        u0.x = pack2h(w0.x, w0.y); u0.y = pack2h(w0.z, w0.w);
        u1.x = pack2h(w1.x, w1.y); u1.y = pack2h(w1.z, w1.w);
        *reinterpret_cast<uint2*>(reinterpret_cast<char*>(sb) + sts0) = u0;
        *reinterpret_cast<uint2*>(reinterpret_cast<char*>(sb) + sts1) = u1;

        if (it + STAGES - 1 < NIT) issue(it + STAGES - 1);
        cp_commit();
        __syncthreads();

        const unsigned sbb = sBh32 + (unsigned)((it & 1) * 4096);
        unsigned afr[4][4];
#pragma unroll
        for (int tm = 0; tm < 4; tm++) {
            int row = wm * 64 + tm * 16 + (lane & 15);
            int kch = it * 2 + (lane >> 4);
            int phys = (kch & ~7) | ((kch & 7) ^ (row & 7));
            ldsm_x4(afr[tm], sA32 + (unsigned)(row * K * 2 + phys * 16));
        }
        unsigned bfr[4][2];
#pragma unroll
        for (int h = 0; h < 2; h++) {
            int nbX  = 2 * h + ((lane >> 4) & 1);
            int c    = ((lane >> 3) & 1) * 8 + (lane & 7);
            int phys = (wn * 4 + nbX) ^ (lane & 7);
            unsigned r4[4];
            ldsm_x4_t(r4, sbb + (unsigned)((c * 128 + phys * 8) * 2));
            bfr[2 * h][0]     = r4[0]; bfr[2 * h][1]     = r4[1];
            bfr[2 * h + 1][0] = r4[2]; bfr[2 * h + 1][1] = r4[3];
        }
#pragma unroll
        for (int tm = 0; tm < 4; tm++)
#pragma unroll
            for (int tn = 0; tn < 4; tn++)
                mma16816(acc[tm][tn], afr[tm], bfr[tn]);
    }

    // epilogue: fp16 store + per-i stats from fp32 accumulators
    __half* yn = yout + (size_t)n * I * S + p0;
#pragma unroll
    for (int tm = 0; tm < 4; tm++) {
        int r1 = wm * 64 + tm * 16 + (lane >> 2);
        float s1 = 0.f, q1 = 0.f, s2 = 0.f, q2 = 0.f;
#pragma unroll
        for (int tn = 0; tn < 4; tn++) {
            float* c = acc[tm][tn];
            int col = wn * 32 + tn * 8 + (lane & 3) * 2;
            *reinterpret_cast<__half2*>(yn + (size_t)r1 * S + col) =
                __floats2half2_rn(c[0], c[1]);
            *reinterpret_cast<__half2*>(yn + (size_t)(r1 + 8) * S + col) =
                __floats2half2_rn(c[2], c[3]);
            s1 += c[0] + c[1]; q1 += c[0] * c[0] + c[1] * c[1];
            s2 += c[2] + c[3]; q2 += c[2] * c[2] + c[3] * c[3];
        }
#pragma unroll
        for (int off = 2; off > 0; off >>= 1) {
            s1 += __shfl_down_sync(0xFFFFFFFFu, s1, off, 4);
            q1 += __shfl_down_sync(0xFFFFFFFFu, q1, off, 4);
            s2 += __shfl_down_sync(0xFFFFFFFFu, s2, off, 4);
            q2 += __shfl_down_sync(0xFFFFFFFFu, q2, off, 4);
        }
        if ((lane & 3) == 0) {
            atomicAdd(&ssum[n * I + r1], s1);
            atomicAdd(&ssq [n * I + r1], q1);
            atomicAdd(&ssum[n * I + r1 + 8], s2);
            atomicAdd(&ssq [n * I + r1 + 8], q2);
        }
    }
}

// ---- coefs ------------------------------------------------------------------
__global__ void k_coefs(const float* __restrict__ gam_g, const float* __restrict__ bet_g,
                        const float* __restrict__ gam_x, const float* __restrict__ bet_x) {
    int t = threadIdx.x;
    if (t < NB * I) {
        int i = t & (I - 1);
        const float inv = 1.f / (float)S;
        float m   = d_sum_g[t] * inv;
        float var = fmaxf(d_sq_g[t] * inv - m * m, 0.f);
        float A   = gam_g[i] * rsqrtf(var + EPS);
        d_cAg[t] = A; d_cBg[t] = bet_g[i] - m * A;
        m   = d_sum_x[t] * inv;
        var = fmaxf(d_sq_x[t] * inv - m * m, 0.f);
        A   = gam_x[i] * rsqrtf(var + EPS);
        d_cAx[t] = A; d_cBx[t] = bet_x[i] - m * A;
    }
}

// ---- combine: z = Wpsi . relu(Ag*yg+Bg + Ax*yx+Bx), + z stats ---------------
__global__ void __launch_bounds__(256) k_combine(const float* __restrict__ Wpsi) {
    __shared__ float sc[5 * I];
    const int tid = threadIdx.x;
    const int n   = blockIdx.y;
    const int p0  = blockIdx.x * 1024;
    if (tid < I) {
        sc[tid]         = d_cAg[n * I + tid];
        sc[I + tid]     = d_cBg[n * I + tid];
        sc[2 * I + tid] = d_cAx[n * I + tid];
        sc[3 * I + tid] = d_cBx[n * I + tid];
        sc[4 * I + tid] = Wpsi[tid];
    }
    __syncthreads();
    const __half* ygb = d_yg + (size_t)n * I * S + p0 + tid * 4;
    const __half* yxb = d_yx + (size_t)n * I * S + p0 + tid * 4;
    float za[4] = {0.f, 0.f, 0.f, 0.f};

#pragma unroll 4
    for (int i = 0; i < I; i++) {
        uint2 ua = *reinterpret_cast<const uint2*>(ygb + (size_t)i * S);
        uint2 ub = *reinterpret_cast<const uint2*>(yxb + (size_t)i * S);
        float Ag = sc[i], Ax = sc[2 * I + i];
        float C  = sc[I + i] + sc[3 * I + i];
        float w  = sc[4 * I + i];
        H2U a0, a1, b0, b1;
        a0.u = ua.x; a1.u = ua.y; b0.u = ub.x; b1.u = ub.y;
        float2 fa0 = __half22float2(a0.h), fa1 = __half22float2(a1.h);
        float2 fb0 = __half22float2(b0.h), fb1 = __half22float2(b1.h);
        za[0] += w * fmaxf(fmaf(Ag, fa0.x, fmaf(Ax, fb0.x, C)), 0.f);
        za[1] += w * fmaxf(fmaf(Ag, fa0.y, fmaf(Ax, fb0.y, C)), 0.f);
        za[2] += w * fmaxf(fmaf(Ag, fa1.x, fmaf(Ax, fb1.x, C)), 0.f);
        za[3] += w * fmaxf(fmaf(Ag, fa1.y, fmaf(Ax, fb1.y, C)), 0.f);
    }
    *reinterpret_cast<float4*>(&d_z[n * S + p0 + tid * 4]) =
        make_float4(za[0], za[1], za[2], za[3]);

    float s = za[0] + za[1] + za[2] + za[3];
    float q = za[0]*za[0] + za[1]*za[1] + za[2]*za[2] + za[3]*za[3];
#pragma unroll
    for (int off = 16; off > 0; off >>= 1) {
        s += __shfl_down_sync(0xFFFFFFFFu, s, off);
        q += __shfl_down_sync(0xFFFFFFFFu, q, off);
    }
    __shared__ float rs[8], rq[8];
    int wid = tid >> 5, ln = tid & 31;
    if (ln == 0) { rs[wid] = s; rq[wid] = q; }
    __syncthreads();
    if (tid == 0) {
        float st = 0.f, qt = 0.f;
#pragma unroll
        for (int w2 = 0; w2 < 8; w2++) { st += rs[w2]; qt += rq[w2]; }
        atomicAdd(&d_zstat[n], st);
        atomicAdd(&d_zstat[NB + n], qt);
    }
}

// ---- fused alpha+mul: out = x * sigmoid(A*z+B) ------------------------------
__global__ void k_mul(const float* __restrict__ x, float* __restrict__ out,
                      const float* __restrict__ gam_p, const float* __restrict__ bet_p) {
    const int idx = blockIdx.x * blockDim.x + threadIdx.x;   // float4 index
    const int n   = idx >> 22;
    const int p4  = idx & (S / 4 - 1);
    const float inv = 1.f / (float)S;
    float m   = d_zstat[n] * inv;
    float var = fmaxf(d_zstat[NB + n] * inv - m * m, 0.f);
    float A   = gam_p[0] * rsqrtf(var + EPS);
    float B   = bet_p[0] - m * A;
    float4 z  = *reinterpret_cast<const float4*>(&d_z[n * S + p4 * 4]);
    float4 xv = reinterpret_cast<const float4*>(x)[idx];
    float4 o;
    o.x = xv.x / (1.f + __expf(-fmaf(A, z.x, B)));
    o.y = xv.y / (1.f + __expf(-fmaf(A, z.y, B)));
    o.z = xv.z / (1.f + __expf(-fmaf(A, z.z, B)));
    o.w = xv.w / (1.f + __expf(-fmaf(A, z.w, B)));
    reinterpret_cast<float4*>(out)[idx] = o;
}

// ============================================================================
extern "C" void kernel_launch(void* const* d_in, const int* in_sizes, int n_in,
                              void* d_out, int out_size) {
    const float* g     = (const float*)d_in[0];
    const float* x     = (const float*)d_in[1];
    const float* Wg    = (const float*)d_in[2];
    const float* Wx    = (const float*)d_in[3];
    const float* Wpsi  = (const float*)d_in[4];
    const float* gam_g = (const float*)d_in[5];
    const float* bet_g = (const float*)d_in[6];
    const float* gam_x = (const float*)d_in[7];
    const float* bet_x = (const float*)d_in[8];
    const float* gam_p = (const float*)d_in[9];
    const float* bet_p = (const float*)d_in[10];
    float* out = (float*)d_out;

    const int SMEM_G = 128 * G  * 2 + STAGES * 8192 + 2 * 4096;   // 106496
    const int SMEM_X = 128 * XC * 2 + STAGES * 8192 + 2 * 4096;   // 73728
    cudaFuncSetAttribute(k_gemm<G,  true >,
                         cudaFuncAttributeMaxDynamicSharedMemorySize, SMEM_G);
    cudaFuncSetAttribute(k_gemm<XC, false>,
                         cudaFuncAttributeMaxDynamicSharedMemorySize, SMEM_X);

    dim3 ggrid(S / 128, NB);                       // 1024 x 2

    // order keeps k_gemm<G> at launch slot 4 (ncu capture)
    k_wconv<<<128, 256>>>(Wg, Wx);
    k_gemm<XC, false><<<ggrid, 256, SMEM_X>>>(x);
    k_zero2<<<1, 32>>>();
    k_gemm<G,  true ><<<ggrid, 256, SMEM_G>>>(g);

    k_coefs<<<1, 256>>>(gam_g, bet_g, gam_x, bet_x);

    dim3 cgrid(S / 1024, NB);                      // 128 x 2
    k_combine<<<cgrid, 256>>>(Wpsi);

    int total4 = NB * XC * S / 4;                  // 16,777,216 float4
    k_mul<<<total4 / 256, 256>>>(x, out, gam_p, bet_p);
}